// round 7
// baseline (speedup 1.0000x reference)
#include <cuda_runtime.h>
#include <cuda_fp16.h>
#include <mma.h>
#include <math.h>
#include <cstdint>
using namespace nvcuda;

#define T_LEN    2048
#define HID      3584
#define QKV_N    4608
#define N_HEADS  28
#define N_REP    7
#define KDIM     3584
#define SCALE    0.08838834764831845f

// ---------------- device scratch ----------------
__device__ __half g_xh[(size_t)T_LEN * HID];
__device__ __half g_wqkvh[(size_t)QKV_N * HID];
__device__ __half g_woh[(size_t)HID * HID];
__device__ __half g_qkvh[(size_t)T_LEN * QKV_N];
__device__ __half g_obufh[(size_t)T_LEN * HID];
__device__ float  g_bqkv[QKV_N];
__device__ float  g_invfreq[64];

// ---------------- PTX helpers ----------------
__device__ __forceinline__ uint32_t smem_u32(const void* p) {
    uint32_t a;
    asm("{ .reg .u64 t; cvta.to.shared.u64 t, %1; cvt.u32.u64 %0, t; }" : "=r"(a) : "l"(p));
    return a;
}
__device__ __forceinline__ void cp_async16(uint32_t dst, const void* src) {
    asm volatile("cp.async.cg.shared.global [%0], [%1], 16;\n" :: "r"(dst), "l"(src) : "memory");
}
__device__ __forceinline__ void ldsm4(uint32_t* r, uint32_t addr) {
    asm volatile("ldmatrix.sync.aligned.m8n8.x4.shared.b16 {%0,%1,%2,%3}, [%4];"
                 : "=r"(r[0]), "=r"(r[1]), "=r"(r[2]), "=r"(r[3]) : "r"(addr));
}
__device__ __forceinline__ void ldsm4t(uint32_t* r, uint32_t addr) {
    asm volatile("ldmatrix.sync.aligned.m8n8.x4.trans.shared.b16 {%0,%1,%2,%3}, [%4];"
                 : "=r"(r[0]), "=r"(r[1]), "=r"(r[2]), "=r"(r[3]) : "r"(addr));
}
__device__ __forceinline__ void mma16816(float* c, const uint32_t* a, const uint32_t* b) {
    asm volatile(
        "mma.sync.aligned.m16n8k16.row.col.f32.f16.f16.f32 "
        "{%0,%1,%2,%3}, {%4,%5,%6,%7}, {%8,%9}, {%0,%1,%2,%3};"
        : "+f"(c[0]), "+f"(c[1]), "+f"(c[2]), "+f"(c[3])
        : "r"(a[0]), "r"(a[1]), "r"(a[2]), "r"(a[3]), "r"(b[0]), "r"(b[1]));
}

// ---------------- prep kernels ----------------
__global__ void prep_small(const float* __restrict__ bq, const float* __restrict__ bk,
                           const float* __restrict__ bv) {
    int i = blockIdx.x * 256 + threadIdx.x;
    if (blockIdx.x == 0 && threadIdx.x < 64)
        g_invfreq[threadIdx.x] = (float)exp(-(double)threadIdx.x / 64.0 * log(10000.0));
    if (i < 3584) g_bqkv[i] = bq[i];
    else if (i < 4096) g_bqkv[i] = bk[i - 3584];
    else if (i < 4608) g_bqkv[i] = bv[i - 4096];
}

// x + wq + wk + wv  (needed before the QKV GEMM)
__global__ void prep_main(const float2* __restrict__ x,  const float2* __restrict__ wq,
                          const float2* __restrict__ wk, const float2* __restrict__ wv) {
    const size_t NX  = (size_t)T_LEN * HID / 2;
    const size_t NWQ = (size_t)HID * HID / 2;
    const size_t NWK = (size_t)512 * HID / 2;
    const size_t TOT = NX + NWQ + 2 * NWK;
    __half2* dx  = (__half2*)g_xh;
    __half2* dwq = (__half2*)g_wqkvh;
    __half2* dwk = (__half2*)(g_wqkvh + (size_t)3584 * HID);
    __half2* dwv = (__half2*)(g_wqkvh + (size_t)4096 * HID);
    size_t stride = (size_t)gridDim.x * blockDim.x;
    for (size_t i = (size_t)blockIdx.x * blockDim.x + threadIdx.x; i < TOT; i += stride) {
        size_t o = i;
        const float2* s; __half2* d;
        if (o < NX)                { s = x;  d = dx;  }
        else if ((o -= NX)  < NWQ) { s = wq; d = dwq; }
        else if ((o -= NWQ) < NWK) { s = wk; d = dwk; }
        else { o -= NWK;             s = wv; d = dwv; }
        float2 v = s[o];
        d[o] = __floats2half2_rn(v.x, v.y);
    }
}

// wo only (needed just before the out-projection — runs on a side stream)
__global__ void prep_wo(const float2* __restrict__ wo) {
    const size_t N = (size_t)HID * HID / 2;
    __half2* d = (__half2*)g_woh;
    size_t stride = (size_t)gridDim.x * blockDim.x;
    for (size_t i = (size_t)blockIdx.x * blockDim.x + threadIdx.x; i < N; i += stride) {
        float2 v = wo[i];
        d[i] = __floats2half2_rn(v.x, v.y);
    }
}

// ---------------- GEMM: C = A[M,K]*B[N,K]^T ----------------
// 128x256 block, 8 warps (2x4), 64x64 warp tile, BK=64, 3-stage cp.async.
// Ch path: half output with fused bias + RoPE (QKV projection).
// Cf path: fp32 output (out projection).
#define GBM 128
#define GBN 256
#define GBK 64
#define GLDA 72
#define GSTAGES 3
#define GSTAGE_H ((GBM + GBN) * GLDA)
#define GSTAGE_BYTES (GSTAGE_H * 2)          // 55296
#define GEMM_SMEM (GSTAGES * GSTAGE_BYTES)   // 165888
#define GNCHUNK (KDIM / GBK)                 // 56
#define STG_LD 260                           // fp32 stage stride

__global__ __launch_bounds__(256)
void gemm_h(const __half* __restrict__ A, const __half* __restrict__ B,
            float* __restrict__ Cf, __half* __restrict__ Ch,
            const float* __restrict__ bias, int ldc)
{
    extern __shared__ __half smh[];
    const uint32_t sbase = smem_u32(smh);
    const int tid = threadIdx.x, warp = tid >> 5;
    const int wm = warp >> 2, wn = warp & 3;

    const long m0 = (long)blockIdx.y * GBM;
    const long n0 = (long)blockIdx.x * GBN;
    const __half* Ab = A + m0 * KDIM;
    const __half* Bb = B + n0 * KDIM;

    wmma::fragment<wmma::accumulator, 16, 16, 16, float> acc[4][4];
    #pragma unroll
    for (int mi = 0; mi < 4; mi++)
        #pragma unroll
        for (int ni = 0; ni < 4; ni++)
            wmma::fill_fragment(acc[mi][ni], 0.0f);

    auto load_chunk = [&](int kc, int s) {
        const __half* ap = Ab + kc * GBK;
        const __half* bp = Bb + kc * GBK;
        uint32_t sA = sbase + s * GSTAGE_BYTES;
        uint32_t sB = sA + GBM * GLDA * 2;
        #pragma unroll
        for (int i = 0; i < 12; i++) {
            int c = tid + i * 256;
            if (c < 1024) {
                int row = c >> 3, seg = (c & 7) * 8;
                cp_async16(sA + (uint32_t)(row * GLDA + seg) * 2, ap + (long)row * KDIM + seg);
            } else {
                int cb = c - 1024;
                int row = cb >> 3, seg = (cb & 7) * 8;
                cp_async16(sB + (uint32_t)(row * GLDA + seg) * 2, bp + (long)row * KDIM + seg);
            }
        }
        asm volatile("cp.async.commit_group;\n" ::: "memory");
    };

    #pragma unroll
    for (int s = 0; s < GSTAGES - 1; s++) load_chunk(s, s);

    for (int k = 0; k < GNCHUNK; k++) {
        if (k < GNCHUNK - 1) {
            asm volatile("cp.async.wait_group 1;\n" ::: "memory");
        } else {
            asm volatile("cp.async.wait_group 0;\n" ::: "memory");
        }
        __syncthreads();
        if (k + GSTAGES - 1 < GNCHUNK) load_chunk(k + GSTAGES - 1, (k + GSTAGES - 1) % GSTAGES);

        const __half* As = smh + (size_t)(k % GSTAGES) * GSTAGE_H;
        const __half* Bs = As + GBM * GLDA;
        #pragma unroll
        for (int kk = 0; kk < 4; kk++) {
            wmma::fragment<wmma::matrix_a, 16, 16, 16, __half, wmma::row_major> af[4];
            #pragma unroll
            for (int mi = 0; mi < 4; mi++)
                wmma::load_matrix_sync(af[mi], As + (wm * 64 + mi * 16) * GLDA + kk * 16, GLDA);
            #pragma unroll
            for (int ni = 0; ni < 4; ni++) {
                wmma::fragment<wmma::matrix_b, 16, 16, 16, __half, wmma::col_major> bf;
                wmma::load_matrix_sync(bf, Bs + (wn * 64 + ni * 16) * GLDA + kk * 16, GLDA);
                #pragma unroll
                for (int mi = 0; mi < 4; mi++)
                    wmma::mma_sync(acc[mi][ni], af[mi], bf, acc[mi][ni]);
            }
        }
    }

    __syncthreads();   // pipeline smem free for staging

    if (Ch) {
        // Stage the entire 128x256 fp32 tile, then bias + RoPE + half store.
        float* stg = (float*)smh;
        #pragma unroll
        for (int mi = 0; mi < 4; mi++)
            #pragma unroll
            for (int ni = 0; ni < 4; ni++)
                wmma::store_matrix_sync(stg + (wm * 64 + mi * 16) * STG_LD + wn * 64 + ni * 16,
                                        acc[mi][ni], STG_LD, wmma::mem_row_major);
        __syncthreads();

        // 128 rows x 2 head-blocks x 16 float4-pairs = 4096 units, 16/thread
        for (int u = tid; u < 128 * 2 * 16; u += 256) {
            int r  = u >> 5;            // 0..127
            int hb = (u >> 4) & 1;      // head block within tile
            int i4 = (u & 15) * 4;      // dim offset 0..60
            long col0 = n0 + hb * 128 + i4;   // global col of x1 part
            const float* sp1 = stg + r * STG_LD + hb * 128 + i4;
            const float* sp2 = sp1 + 64;
            float4 x1 = *(const float4*)sp1;
            float4 x2 = *(const float4*)sp2;
            const float* b1 = bias + col0;
            x1.x += b1[0];  x1.y += b1[1];  x1.z += b1[2];  x1.w += b1[3];
            x2.x += b1[64]; x2.y += b1[65]; x2.z += b1[66]; x2.w += b1[67];
            long gr = m0 + r;
            __half2 o1a, o1b, o2a, o2b;
            if (col0 < 4096) {   // q or k head: rope
                float t = (float)gr;
                float s0, c0, s1c, c1, s2, c2, s3, c3;
                sincosf(t * g_invfreq[i4 + 0], &s0, &c0);
                sincosf(t * g_invfreq[i4 + 1], &s1c, &c1);
                sincosf(t * g_invfreq[i4 + 2], &s2, &c2);
                sincosf(t * g_invfreq[i4 + 3], &s3, &c3);
                o1a = __floats2half2_rn(x1.x * c0 - x2.x * s0,  x1.y * c1 - x2.y * s1c);
                o1b = __floats2half2_rn(x1.z * c2 - x2.z * s2,  x1.w * c3 - x2.w * s3);
                o2a = __floats2half2_rn(x2.x * c0 + x1.x * s0,  x2.y * c1 + x1.y * s1c);
                o2b = __floats2half2_rn(x2.z * c2 + x1.z * s2,  x2.w * c3 + x1.w * s3);
            } else {             // v head: bias only
                o1a = __floats2half2_rn(x1.x, x1.y);
                o1b = __floats2half2_rn(x1.z, x1.w);
                o2a = __floats2half2_rn(x2.x, x2.y);
                o2b = __floats2half2_rn(x2.z, x2.w);
            }
            __half* d1 = Ch + gr * (long)ldc + col0;
            uint2 w1; w1.x = *(uint32_t*)&o1a; w1.y = *(uint32_t*)&o1b;
            uint2 w2; w2.x = *(uint32_t*)&o2a; w2.y = *(uint32_t*)&o2b;
            *(uint2*)d1 = w1;
            *(uint2*)(d1 + 64) = w2;
        }
    } else {
        #pragma unroll
        for (int mi = 0; mi < 4; mi++)
            #pragma unroll
            for (int ni = 0; ni < 4; ni++) {
                float* cp = Cf + (m0 + wm * 64 + mi * 16) * (long)ldc + n0 + wn * 64 + ni * 16;
                wmma::store_matrix_sync(cp, acc[mi][ni], ldc, wmma::mem_row_major);
            }
    }
}

// ---------------- FA2-style attention (unchanged) ----------------
#define AQB 128
#define AKB 64
#define LDK 136
#define ATTN_SMEM_BYTES ((AQB * LDK + 2 * 2 * AKB * LDK) * 2)

__global__ __launch_bounds__(256)
void attn_kernel()
{
    extern __shared__ __half sm[];
    const uint32_t sbase = smem_u32(sm);
    const int qb = blockIdx.x, h = blockIdx.y, kvh = h / N_REP;
    const int tid = threadIdx.x, w = tid >> 5, lane = tid & 31;

    const __half* qg = g_qkvh + (size_t)(qb * AQB) * QKV_N + h * 128;
    #pragma unroll
    for (int i = 0; i < 8; i++) {
        int lin = tid + i * 256;
        int r = lin >> 4, seg = (lin & 15) * 8;
        *(uint4*)&sm[r * LDK + seg] = *(const uint4*)(qg + (size_t)r * QKV_N + seg);
    }

    auto kvload = [&](int kb, int s) {
        const __half* kg = g_qkvh + (size_t)(kb * AKB) * QKV_N + 3584 + kvh * 128;
        const __half* vg = g_qkvh + (size_t)(kb * AKB) * QKV_N + 4096 + kvh * 128;
        uint32_t kb_s = sbase + (uint32_t)(AQB * LDK + s * 2 * AKB * LDK) * 2;
        uint32_t vb_s = kb_s + AKB * LDK * 2;
        #pragma unroll
        for (int i = 0; i < 4; i++) {
            int lin = tid + i * 256;
            int r = lin >> 4, seg = (lin & 15) * 8;
            uint32_t off = (uint32_t)(r * LDK + seg) * 2;
            cp_async16(kb_s + off, kg + (size_t)r * QKV_N + seg);
            cp_async16(vb_s + off, vg + (size_t)r * QKV_N + seg);
        }
        asm volatile("cp.async.commit_group;\n" ::: "memory");
    };
    kvload(0, 0);
    __syncthreads();

    uint32_t qf[8][4];
    {
        int quad = lane >> 3, r = lane & 7;
        int qrow = w * 16 + (quad & 1) * 8 + r;
        #pragma unroll
        for (int kk = 0; kk < 8; kk++) {
            uint32_t addr = sbase + (uint32_t)(qrow * LDK + kk * 16 + (quad >> 1) * 8) * 2;
            ldsm4(qf[kk], addr);
        }
    }

    float of[16][4];
    #pragma unroll
    for (int j = 0; j < 16; j++) { of[j][0] = of[j][1] = of[j][2] = of[j][3] = 0.f; }
    float m0 = -INFINITY, m1 = -INFINITY, l0 = 0.f, l1 = 0.f;

    const int quad = lane >> 3, r8 = lane & 7;
    const int k_rowoff = (quad >> 1) * 8 + r8;
    const int k_coloff = (quad & 1) * 8;
    const int v_rowoff = (quad & 1) * 8 + r8;
    const int v_coloff = (quad >> 1) * 8;

    for (int kb = 0; kb < T_LEN / AKB; kb++) {
        if (kb + 1 < T_LEN / AKB) {
            kvload(kb + 1, (kb + 1) & 1);
            asm volatile("cp.async.wait_group 1;\n" ::: "memory");
        } else {
            asm volatile("cp.async.wait_group 0;\n" ::: "memory");
        }
        __syncthreads();

        uint32_t kbase = sbase + (uint32_t)(AQB * LDK + (kb & 1) * 2 * AKB * LDK) * 2;
        uint32_t vbase = kbase + AKB * LDK * 2;

        float sf[8][4];
        #pragma unroll
        for (int j = 0; j < 8; j++) { sf[j][0] = sf[j][1] = sf[j][2] = sf[j][3] = 0.f; }
        #pragma unroll
        for (int jp = 0; jp < 4; jp++) {
            #pragma unroll
            for (int kk = 0; kk < 8; kk++) {
                uint32_t addr = kbase + (uint32_t)((jp * 16 + k_rowoff) * LDK + kk * 16 + k_coloff) * 2;
                uint32_t b[4];
                ldsm4(b, addr);
                mma16816(sf[2 * jp],     qf[kk], b);
                mma16816(sf[2 * jp + 1], qf[kk], b + 2);
            }
        }

        float mx0 = -INFINITY, mx1 = -INFINITY;
        #pragma unroll
        for (int j = 0; j < 8; j++) {
            mx0 = fmaxf(mx0, fmaxf(sf[j][0], sf[j][1]));
            mx1 = fmaxf(mx1, fmaxf(sf[j][2], sf[j][3]));
        }
        mx0 = fmaxf(mx0, __shfl_xor_sync(0xffffffffu, mx0, 1));
        mx0 = fmaxf(mx0, __shfl_xor_sync(0xffffffffu, mx0, 2));
        mx1 = fmaxf(mx1, __shfl_xor_sync(0xffffffffu, mx1, 1));
        mx1 = fmaxf(mx1, __shfl_xor_sync(0xffffffffu, mx1, 2));

        float mn0 = fmaxf(m0, mx0 * SCALE);
        float mn1 = fmaxf(m1, mx1 * SCALE);
        float a0 = __expf(m0 - mn0);
        float a1 = __expf(m1 - mn1);

        uint32_t ph[8][2];
        float s0 = 0.f, s1 = 0.f;
        #pragma unroll
        for (int j = 0; j < 8; j++) {
            float p0 = __expf(sf[j][0] * SCALE - mn0);
            float p1 = __expf(sf[j][1] * SCALE - mn0);
            float p2 = __expf(sf[j][2] * SCALE - mn1);
            float p3 = __expf(sf[j][3] * SCALE - mn1);
            s0 += p0 + p1; s1 += p2 + p3;
            __half2 h01 = __floats2half2_rn(p0, p1);
            __half2 h23 = __floats2half2_rn(p2, p3);
            ph[j][0] = *(uint32_t*)&h01;
            ph[j][1] = *(uint32_t*)&h23;
        }
        s0 += __shfl_xor_sync(0xffffffffu, s0, 1);
        s0 += __shfl_xor_sync(0xffffffffu, s0, 2);
        s1 += __shfl_xor_sync(0xffffffffu, s1, 1);
        s1 += __shfl_xor_sync(0xffffffffu, s1, 2);
        l0 = l0 * a0 + s0;
        l1 = l1 * a1 + s1;
        m0 = mn0; m1 = mn1;

        #pragma unroll
        for (int j = 0; j < 16; j++) {
            of[j][0] *= a0; of[j][1] *= a0;
            of[j][2] *= a1; of[j][3] *= a1;
        }

        uint32_t pa[4][4];
        #pragma unroll
        for (int kk = 0; kk < 4; kk++) {
            pa[kk][0] = ph[2 * kk][0];
            pa[kk][1] = ph[2 * kk][1];
            pa[kk][2] = ph[2 * kk + 1][0];
            pa[kk][3] = ph[2 * kk + 1][1];
        }
        #pragma unroll
        for (int jp = 0; jp < 8; jp++) {
            #pragma unroll
            for (int kk = 0; kk < 4; kk++) {
                uint32_t addr = vbase + (uint32_t)((kk * 16 + v_rowoff) * LDK + jp * 16 + v_coloff) * 2;
                uint32_t b[4];
                ldsm4t(b, addr);
                mma16816(of[2 * jp],     pa[kk], b);
                mma16816(of[2 * jp + 1], pa[kk], b + 2);
            }
        }
        __syncthreads();
    }

    float inv0 = 1.f / l0, inv1 = 1.f / l1;
    int row_lo = qb * AQB + w * 16 + (lane >> 2);
    int tig = lane & 3;
    #pragma unroll
    for (int j = 0; j < 16; j++) {
        int col = h * 128 + j * 8 + tig * 2;
        __half2 o01 = __floats2half2_rn(of[j][0] * inv0, of[j][1] * inv0);
        __half2 o23 = __floats2half2_rn(of[j][2] * inv1, of[j][3] * inv1);
        *(__half2*)&g_obufh[(size_t)row_lo * HID + col] = o01;
        *(__half2*)&g_obufh[(size_t)(row_lo + 8) * HID + col] = o23;
    }
}

// ---------------- launch ----------------
extern "C" void kernel_launch(void* const* d_in, const int* in_sizes, int n_in,
                              void* d_out, int out_size)
{
    (void)in_sizes; (void)n_in; (void)out_size;
    const float* x  = (const float*)d_in[1];
    const float* wq = (const float*)d_in[2];
    const float* bq = (const float*)d_in[3];
    const float* wk = (const float*)d_in[4];
    const float* bk = (const float*)d_in[5];
    const float* wv = (const float*)d_in[6];
    const float* bv = (const float*)d_in[7];
    const float* wo = (const float*)d_in[8];
    float* out = (float*)d_out;

    void *xh, *wqkvh, *woh, *qkvhp, *obufhp, *bqkvp;
    cudaGetSymbolAddress(&xh, g_xh);
    cudaGetSymbolAddress(&wqkvh, g_wqkvh);
    cudaGetSymbolAddress(&woh, g_woh);
    cudaGetSymbolAddress(&qkvhp, g_qkvh);
    cudaGetSymbolAddress(&obufhp, g_obufh);
    cudaGetSymbolAddress(&bqkvp, g_bqkv);

    cudaFuncSetAttribute(gemm_h, cudaFuncAttributeMaxDynamicSharedMemorySize, GEMM_SMEM);
    cudaFuncSetAttribute(attn_kernel, cudaFuncAttributeMaxDynamicSharedMemorySize, ATTN_SMEM_BYTES);

    // One-time side-stream setup (no allocs; created once, reused)
    static cudaStream_t s_side = nullptr;
    static cudaEvent_t ev_fork = nullptr, ev_join = nullptr;
    if (!s_side) {
        if (cudaStreamCreateWithFlags(&s_side, cudaStreamNonBlocking) != cudaSuccess) s_side = nullptr;
        if (s_side) {
            cudaEventCreateWithFlags(&ev_fork, cudaEventDisableTiming);
            cudaEventCreateWithFlags(&ev_join, cudaEventDisableTiming);
        }
    }

    prep_small<<<18, 256>>>(bq, bk, bv);
    prep_main<<<1536, 256>>>((const float2*)x, (const float2*)wq,
                             (const float2*)wk, (const float2*)wv);

    if (s_side) {
        // fork: wo conversion overlaps QKV GEMM + attention
        cudaEventRecord(ev_fork, 0);
        cudaStreamWaitEvent(s_side, ev_fork, 0);
        prep_wo<<<512, 256, 0, s_side>>>((const float2*)wo);
        cudaEventRecord(ev_join, s_side);
    } else {
        prep_wo<<<512, 256>>>((const float2*)wo);
    }

    // fused QKV projection: half output + fused bias + RoPE
    gemm_h<<<dim3(QKV_N / GBN, T_LEN / GBM), 256, GEMM_SMEM>>>(
        (const __half*)xh, (const __half*)wqkvh, nullptr, (__half*)qkvhp,
        (const float*)bqkvp, QKV_N);

    attn_kernel<<<dim3(T_LEN / AQB, N_HEADS), 256, ATTN_SMEM_BYTES>>>();

    if (s_side) cudaStreamWaitEvent(0, ev_join, 0);   // join before out-proj

    gemm_h<<<dim3(HID / GBN, T_LEN / GBM), 256, GEMM_SMEM>>>(
        (const __half*)obufhp, (const __half*)woh, out, nullptr, nullptr, HID);
}

// round 8
// speedup vs baseline: 1.0125x; 1.0125x over previous
#include <cuda_runtime.h>
#include <cuda_fp16.h>
#include <mma.h>
#include <math.h>
#include <cstdint>
using namespace nvcuda;

#define T_LEN    2048
#define HID      3584
#define QKV_N    4608
#define N_HEADS  28
#define N_REP    7
#define KDIM     3584
#define SCALE    0.08838834764831845f

// ---------------- device scratch ----------------
__device__ __half g_xh[(size_t)T_LEN * HID];
__device__ __half g_wqkvh[(size_t)QKV_N * HID];
__device__ __half g_woh[(size_t)HID * HID];
__device__ __half g_qkvh[(size_t)T_LEN * QKV_N];
__device__ __half g_obufh[(size_t)T_LEN * HID];
__device__ float  g_bqkv[QKV_N];
__device__ float  g_invfreq[64];

// ---------------- PTX helpers ----------------
__device__ __forceinline__ uint32_t smem_u32(const void* p) {
    uint32_t a;
    asm("{ .reg .u64 t; cvta.to.shared.u64 t, %1; cvt.u32.u64 %0, t; }" : "=r"(a) : "l"(p));
    return a;
}
__device__ __forceinline__ void cp_async16(uint32_t dst, const void* src) {
    asm volatile("cp.async.cg.shared.global [%0], [%1], 16;\n" :: "r"(dst), "l"(src) : "memory");
}
__device__ __forceinline__ void ldsm4(uint32_t* r, uint32_t addr) {
    asm volatile("ldmatrix.sync.aligned.m8n8.x4.shared.b16 {%0,%1,%2,%3}, [%4];"
                 : "=r"(r[0]), "=r"(r[1]), "=r"(r[2]), "=r"(r[3]) : "r"(addr));
}
__device__ __forceinline__ void ldsm4t(uint32_t* r, uint32_t addr) {
    asm volatile("ldmatrix.sync.aligned.m8n8.x4.trans.shared.b16 {%0,%1,%2,%3}, [%4];"
                 : "=r"(r[0]), "=r"(r[1]), "=r"(r[2]), "=r"(r[3]) : "r"(addr));
}
__device__ __forceinline__ void mma16816(float* c, const uint32_t* a, const uint32_t* b) {
    asm volatile(
        "mma.sync.aligned.m16n8k16.row.col.f32.f16.f16.f32 "
        "{%0,%1,%2,%3}, {%4,%5,%6,%7}, {%8,%9}, {%0,%1,%2,%3};"
        : "+f"(c[0]), "+f"(c[1]), "+f"(c[2]), "+f"(c[3])
        : "r"(a[0]), "r"(a[1]), "r"(a[2]), "r"(a[3]), "r"(b[0]), "r"(b[1]));
}

// ---------------- prep kernels ----------------
__global__ void prep_small(const float* __restrict__ bq, const float* __restrict__ bk,
                           const float* __restrict__ bv) {
    int i = blockIdx.x * 256 + threadIdx.x;
    if (blockIdx.x == 0 && threadIdx.x < 64)
        g_invfreq[threadIdx.x] = (float)exp(-(double)threadIdx.x / 64.0 * log(10000.0));
    if (i < 3584) g_bqkv[i] = bq[i];
    else if (i < 4096) g_bqkv[i] = bk[i - 3584];
    else if (i < 4608) g_bqkv[i] = bv[i - 4096];
}

__global__ void prep_main(const float2* __restrict__ x,  const float2* __restrict__ wq,
                          const float2* __restrict__ wk, const float2* __restrict__ wv) {
    const size_t NX  = (size_t)T_LEN * HID / 2;
    const size_t NWQ = (size_t)HID * HID / 2;
    const size_t NWK = (size_t)512 * HID / 2;
    const size_t TOT = NX + NWQ + 2 * NWK;
    __half2* dx  = (__half2*)g_xh;
    __half2* dwq = (__half2*)g_wqkvh;
    __half2* dwk = (__half2*)(g_wqkvh + (size_t)3584 * HID);
    __half2* dwv = (__half2*)(g_wqkvh + (size_t)4096 * HID);
    size_t stride = (size_t)gridDim.x * blockDim.x;
    for (size_t i = (size_t)blockIdx.x * blockDim.x + threadIdx.x; i < TOT; i += stride) {
        size_t o = i;
        const float2* s; __half2* d;
        if (o < NX)                { s = x;  d = dx;  }
        else if ((o -= NX)  < NWQ) { s = wq; d = dwq; }
        else if ((o -= NWQ) < NWK) { s = wk; d = dwk; }
        else { o -= NWK;             s = wv; d = dwv; }
        float2 v = s[o];
        d[o] = __floats2half2_rn(v.x, v.y);
    }
}

__global__ void prep_wo(const float2* __restrict__ wo) {
    const size_t N = (size_t)HID * HID / 2;
    __half2* d = (__half2*)g_woh;
    size_t stride = (size_t)gridDim.x * blockDim.x;
    for (size_t i = (size_t)blockIdx.x * blockDim.x + threadIdx.x; i < N; i += stride) {
        float2 v = wo[i];
        d[i] = __floats2half2_rn(v.x, v.y);
    }
}

// ---------------- GEMM: C = A[M,K]*B[N,K]^T ----------------
// 128x256 CTA tile, 512 threads = 16 warps (2x8), warp tile 64x32,
// BK=64, 3-stage cp.async. Ch path: half out + fused bias + RoPE.
#define GBM 128
#define GBN 256
#define GBK 64
#define GLDA 72
#define GSTAGES 3
#define GSTAGE_H ((GBM + GBN) * GLDA)
#define GSTAGE_BYTES (GSTAGE_H * 2)          // 55296
#define GEMM_SMEM (GSTAGES * GSTAGE_BYTES)   // 165888
#define GNCHUNK (KDIM / GBK)                 // 56
#define STG_LD 260

__global__ __launch_bounds__(512, 1)
void gemm_h(const __half* __restrict__ A, const __half* __restrict__ B,
            float* __restrict__ Cf, __half* __restrict__ Ch,
            const float* __restrict__ bias, int ldc)
{
    extern __shared__ __half smh[];
    const uint32_t sbase = smem_u32(smh);
    const int tid = threadIdx.x, warp = tid >> 5;
    const int wm = warp >> 3, wn = warp & 7;    // 2 x 8 warp grid, 64x32 tiles

    const long m0 = (long)blockIdx.y * GBM;
    const long n0 = (long)blockIdx.x * GBN;
    const __half* Ab = A + m0 * KDIM;
    const __half* Bb = B + n0 * KDIM;

    wmma::fragment<wmma::accumulator, 16, 16, 16, float> acc[4][2];
    #pragma unroll
    for (int mi = 0; mi < 4; mi++)
        #pragma unroll
        for (int ni = 0; ni < 2; ni++)
            wmma::fill_fragment(acc[mi][ni], 0.0f);

    auto load_chunk = [&](int kc, int s) {
        const __half* ap = Ab + kc * GBK;
        const __half* bp = Bb + kc * GBK;
        uint32_t sA = sbase + s * GSTAGE_BYTES;
        uint32_t sB = sA + GBM * GLDA * 2;
        #pragma unroll
        for (int i = 0; i < 6; i++) {
            int c = tid + i * 512;               // 0..3071
            if (c < 1024) {
                int row = c >> 3, seg = (c & 7) * 8;
                cp_async16(sA + (uint32_t)(row * GLDA + seg) * 2, ap + (long)row * KDIM + seg);
            } else {
                int cb = c - 1024;
                int row = cb >> 3, seg = (cb & 7) * 8;
                cp_async16(sB + (uint32_t)(row * GLDA + seg) * 2, bp + (long)row * KDIM + seg);
            }
        }
        asm volatile("cp.async.commit_group;\n" ::: "memory");
    };

    #pragma unroll
    for (int s = 0; s < GSTAGES - 1; s++) load_chunk(s, s);

    for (int k = 0; k < GNCHUNK; k++) {
        if (k < GNCHUNK - 1) {
            asm volatile("cp.async.wait_group 1;\n" ::: "memory");
        } else {
            asm volatile("cp.async.wait_group 0;\n" ::: "memory");
        }
        __syncthreads();
        if (k + GSTAGES - 1 < GNCHUNK) load_chunk(k + GSTAGES - 1, (k + GSTAGES - 1) % GSTAGES);

        const __half* As = smh + (size_t)(k % GSTAGES) * GSTAGE_H;
        const __half* Bs = As + GBM * GLDA;
        #pragma unroll
        for (int kk = 0; kk < 4; kk++) {
            wmma::fragment<wmma::matrix_a, 16, 16, 16, __half, wmma::row_major> af[4];
            #pragma unroll
            for (int mi = 0; mi < 4; mi++)
                wmma::load_matrix_sync(af[mi], As + (wm * 64 + mi * 16) * GLDA + kk * 16, GLDA);
            #pragma unroll
            for (int ni = 0; ni < 2; ni++) {
                wmma::fragment<wmma::matrix_b, 16, 16, 16, __half, wmma::col_major> bf;
                wmma::load_matrix_sync(bf, Bs + (wn * 32 + ni * 16) * GLDA + kk * 16, GLDA);
                #pragma unroll
                for (int mi = 0; mi < 4; mi++)
                    wmma::mma_sync(acc[mi][ni], af[mi], bf, acc[mi][ni]);
            }
        }
    }

    __syncthreads();   // pipeline smem free for staging

    if (Ch) {
        float* stg = (float*)smh;
        #pragma unroll
        for (int mi = 0; mi < 4; mi++)
            #pragma unroll
            for (int ni = 0; ni < 2; ni++)
                wmma::store_matrix_sync(stg + (wm * 64 + mi * 16) * STG_LD + wn * 32 + ni * 16,
                                        acc[mi][ni], STG_LD, wmma::mem_row_major);
        __syncthreads();

        // 128 rows x 2 head-blocks x 16 float4-pairs = 4096 units
        for (int u = tid; u < 128 * 2 * 16; u += 512) {
            int r  = u >> 5;
            int hb = (u >> 4) & 1;
            int i4 = (u & 15) * 4;
            long col0 = n0 + hb * 128 + i4;
            const float* sp1 = stg + r * STG_LD + hb * 128 + i4;
            const float* sp2 = sp1 + 64;
            float4 x1 = *(const float4*)sp1;
            float4 x2 = *(const float4*)sp2;
            const float* b1 = bias + col0;
            x1.x += b1[0];  x1.y += b1[1];  x1.z += b1[2];  x1.w += b1[3];
            x2.x += b1[64]; x2.y += b1[65]; x2.z += b1[66]; x2.w += b1[67];
            long gr = m0 + r;
            __half2 o1a, o1b, o2a, o2b;
            if (col0 < 4096) {
                float t = (float)gr;
                float s0, c0, s1c, c1, s2, c2, s3, c3;
                sincosf(t * g_invfreq[i4 + 0], &s0, &c0);
                sincosf(t * g_invfreq[i4 + 1], &s1c, &c1);
                sincosf(t * g_invfreq[i4 + 2], &s2, &c2);
                sincosf(t * g_invfreq[i4 + 3], &s3, &c3);
                o1a = __floats2half2_rn(x1.x * c0 - x2.x * s0,  x1.y * c1 - x2.y * s1c);
                o1b = __floats2half2_rn(x1.z * c2 - x2.z * s2,  x1.w * c3 - x2.w * s3);
                o2a = __floats2half2_rn(x2.x * c0 + x1.x * s0,  x2.y * c1 + x1.y * s1c);
                o2b = __floats2half2_rn(x2.z * c2 + x1.z * s2,  x2.w * c3 + x1.w * s3);
            } else {
                o1a = __floats2half2_rn(x1.x, x1.y);
                o1b = __floats2half2_rn(x1.z, x1.w);
                o2a = __floats2half2_rn(x2.x, x2.y);
                o2b = __floats2half2_rn(x2.z, x2.w);
            }
            __half* d1 = Ch + gr * (long)ldc + col0;
            uint2 w1; w1.x = *(uint32_t*)&o1a; w1.y = *(uint32_t*)&o1b;
            uint2 w2; w2.x = *(uint32_t*)&o2a; w2.y = *(uint32_t*)&o2b;
            *(uint2*)d1 = w1;
            *(uint2*)(d1 + 64) = w2;
        }
    } else {
        #pragma unroll
        for (int mi = 0; mi < 4; mi++)
            #pragma unroll
            for (int ni = 0; ni < 2; ni++) {
                float* cp = Cf + (m0 + wm * 64 + mi * 16) * (long)ldc + n0 + wn * 32 + ni * 16;
                wmma::store_matrix_sync(cp, acc[mi][ni], ldc, wmma::mem_row_major);
            }
    }
}

// ---------------- FA2-style attention (unchanged) ----------------
#define AQB 128
#define AKB 64
#define LDK 136
#define ATTN_SMEM_BYTES ((AQB * LDK + 2 * 2 * AKB * LDK) * 2)

__global__ __launch_bounds__(256)
void attn_kernel()
{
    extern __shared__ __half sm[];
    const uint32_t sbase = smem_u32(sm);
    const int qb = blockIdx.x, h = blockIdx.y, kvh = h / N_REP;
    const int tid = threadIdx.x, w = tid >> 5, lane = tid & 31;

    const __half* qg = g_qkvh + (size_t)(qb * AQB) * QKV_N + h * 128;
    #pragma unroll
    for (int i = 0; i < 8; i++) {
        int lin = tid + i * 256;
        int r = lin >> 4, seg = (lin & 15) * 8;
        *(uint4*)&sm[r * LDK + seg] = *(const uint4*)(qg + (size_t)r * QKV_N + seg);
    }

    auto kvload = [&](int kb, int s) {
        const __half* kg = g_qkvh + (size_t)(kb * AKB) * QKV_N + 3584 + kvh * 128;
        const __half* vg = g_qkvh + (size_t)(kb * AKB) * QKV_N + 4096 + kvh * 128;
        uint32_t kb_s = sbase + (uint32_t)(AQB * LDK + s * 2 * AKB * LDK) * 2;
        uint32_t vb_s = kb_s + AKB * LDK * 2;
        #pragma unroll
        for (int i = 0; i < 4; i++) {
            int lin = tid + i * 256;
            int r = lin >> 4, seg = (lin & 15) * 8;
            uint32_t off = (uint32_t)(r * LDK + seg) * 2;
            cp_async16(kb_s + off, kg + (size_t)r * QKV_N + seg);
            cp_async16(vb_s + off, vg + (size_t)r * QKV_N + seg);
        }
        asm volatile("cp.async.commit_group;\n" ::: "memory");
    };
    kvload(0, 0);
    __syncthreads();

    uint32_t qf[8][4];
    {
        int quad = lane >> 3, r = lane & 7;
        int qrow = w * 16 + (quad & 1) * 8 + r;
        #pragma unroll
        for (int kk = 0; kk < 8; kk++) {
            uint32_t addr = sbase + (uint32_t)(qrow * LDK + kk * 16 + (quad >> 1) * 8) * 2;
            ldsm4(qf[kk], addr);
        }
    }

    float of[16][4];
    #pragma unroll
    for (int j = 0; j < 16; j++) { of[j][0] = of[j][1] = of[j][2] = of[j][3] = 0.f; }
    float m0 = -INFINITY, m1 = -INFINITY, l0 = 0.f, l1 = 0.f;

    const int quad = lane >> 3, r8 = lane & 7;
    const int k_rowoff = (quad >> 1) * 8 + r8;
    const int k_coloff = (quad & 1) * 8;
    const int v_rowoff = (quad & 1) * 8 + r8;
    const int v_coloff = (quad >> 1) * 8;

    for (int kb = 0; kb < T_LEN / AKB; kb++) {
        if (kb + 1 < T_LEN / AKB) {
            kvload(kb + 1, (kb + 1) & 1);
            asm volatile("cp.async.wait_group 1;\n" ::: "memory");
        } else {
            asm volatile("cp.async.wait_group 0;\n" ::: "memory");
        }
        __syncthreads();

        uint32_t kbase = sbase + (uint32_t)(AQB * LDK + (kb & 1) * 2 * AKB * LDK) * 2;
        uint32_t vbase = kbase + AKB * LDK * 2;

        float sf[8][4];
        #pragma unroll
        for (int j = 0; j < 8; j++) { sf[j][0] = sf[j][1] = sf[j][2] = sf[j][3] = 0.f; }
        #pragma unroll
        for (int jp = 0; jp < 4; jp++) {
            #pragma unroll
            for (int kk = 0; kk < 8; kk++) {
                uint32_t addr = kbase + (uint32_t)((jp * 16 + k_rowoff) * LDK + kk * 16 + k_coloff) * 2;
                uint32_t b[4];
                ldsm4(b, addr);
                mma16816(sf[2 * jp],     qf[kk], b);
                mma16816(sf[2 * jp + 1], qf[kk], b + 2);
            }
        }

        float mx0 = -INFINITY, mx1 = -INFINITY;
        #pragma unroll
        for (int j = 0; j < 8; j++) {
            mx0 = fmaxf(mx0, fmaxf(sf[j][0], sf[j][1]));
            mx1 = fmaxf(mx1, fmaxf(sf[j][2], sf[j][3]));
        }
        mx0 = fmaxf(mx0, __shfl_xor_sync(0xffffffffu, mx0, 1));
        mx0 = fmaxf(mx0, __shfl_xor_sync(0xffffffffu, mx0, 2));
        mx1 = fmaxf(mx1, __shfl_xor_sync(0xffffffffu, mx1, 1));
        mx1 = fmaxf(mx1, __shfl_xor_sync(0xffffffffu, mx1, 2));

        float mn0 = fmaxf(m0, mx0 * SCALE);
        float mn1 = fmaxf(m1, mx1 * SCALE);
        float a0 = __expf(m0 - mn0);
        float a1 = __expf(m1 - mn1);

        uint32_t ph[8][2];
        float s0 = 0.f, s1 = 0.f;
        #pragma unroll
        for (int j = 0; j < 8; j++) {
            float p0 = __expf(sf[j][0] * SCALE - mn0);
            float p1 = __expf(sf[j][1] * SCALE - mn0);
            float p2 = __expf(sf[j][2] * SCALE - mn1);
            float p3 = __expf(sf[j][3] * SCALE - mn1);
            s0 += p0 + p1; s1 += p2 + p3;
            __half2 h01 = __floats2half2_rn(p0, p1);
            __half2 h23 = __floats2half2_rn(p2, p3);
            ph[j][0] = *(uint32_t*)&h01;
            ph[j][1] = *(uint32_t*)&h23;
        }
        s0 += __shfl_xor_sync(0xffffffffu, s0, 1);
        s0 += __shfl_xor_sync(0xffffffffu, s0, 2);
        s1 += __shfl_xor_sync(0xffffffffu, s1, 1);
        s1 += __shfl_xor_sync(0xffffffffu, s1, 2);
        l0 = l0 * a0 + s0;
        l1 = l1 * a1 + s1;
        m0 = mn0; m1 = mn1;

        #pragma unroll
        for (int j = 0; j < 16; j++) {
            of[j][0] *= a0; of[j][1] *= a0;
            of[j][2] *= a1; of[j][3] *= a1;
        }

        uint32_t pa[4][4];
        #pragma unroll
        for (int kk = 0; kk < 4; kk++) {
            pa[kk][0] = ph[2 * kk][0];
            pa[kk][1] = ph[2 * kk][1];
            pa[kk][2] = ph[2 * kk + 1][0];
            pa[kk][3] = ph[2 * kk + 1][1];
        }
        #pragma unroll
        for (int jp = 0; jp < 8; jp++) {
            #pragma unroll
            for (int kk = 0; kk < 4; kk++) {
                uint32_t addr = vbase + (uint32_t)((kk * 16 + v_rowoff) * LDK + jp * 16 + v_coloff) * 2;
                uint32_t b[4];
                ldsm4t(b, addr);
                mma16816(of[2 * jp],     pa[kk], b);
                mma16816(of[2 * jp + 1], pa[kk], b + 2);
            }
        }
        __syncthreads();
    }

    float inv0 = 1.f / l0, inv1 = 1.f / l1;
    int row_lo = qb * AQB + w * 16 + (lane >> 2);
    int tig = lane & 3;
    #pragma unroll
    for (int j = 0; j < 16; j++) {
        int col = h * 128 + j * 8 + tig * 2;
        __half2 o01 = __floats2half2_rn(of[j][0] * inv0, of[j][1] * inv0);
        __half2 o23 = __floats2half2_rn(of[j][2] * inv1, of[j][3] * inv1);
        *(__half2*)&g_obufh[(size_t)row_lo * HID + col] = o01;
        *(__half2*)&g_obufh[(size_t)(row_lo + 8) * HID + col] = o23;
    }
}

// ---------------- launch ----------------
extern "C" void kernel_launch(void* const* d_in, const int* in_sizes, int n_in,
                              void* d_out, int out_size)
{
    (void)in_sizes; (void)n_in; (void)out_size;
    const float* x  = (const float*)d_in[1];
    const float* wq = (const float*)d_in[2];
    const float* bq = (const float*)d_in[3];
    const float* wk = (const float*)d_in[4];
    const float* bk = (const float*)d_in[5];
    const float* wv = (const float*)d_in[6];
    const float* bv = (const float*)d_in[7];
    const float* wo = (const float*)d_in[8];
    float* out = (float*)d_out;

    void *xh, *wqkvh, *woh, *qkvhp, *obufhp, *bqkvp;
    cudaGetSymbolAddress(&xh, g_xh);
    cudaGetSymbolAddress(&wqkvh, g_wqkvh);
    cudaGetSymbolAddress(&woh, g_woh);
    cudaGetSymbolAddress(&qkvhp, g_qkvh);
    cudaGetSymbolAddress(&obufhp, g_obufh);
    cudaGetSymbolAddress(&bqkvp, g_bqkv);

    cudaFuncSetAttribute(gemm_h, cudaFuncAttributeMaxDynamicSharedMemorySize, GEMM_SMEM);
    cudaFuncSetAttribute(attn_kernel, cudaFuncAttributeMaxDynamicSharedMemorySize, ATTN_SMEM_BYTES);

    static cudaStream_t s_side = nullptr;
    static cudaEvent_t ev_fork = nullptr, ev_join = nullptr;
    if (!s_side) {
        if (cudaStreamCreateWithFlags(&s_side, cudaStreamNonBlocking) != cudaSuccess) s_side = nullptr;
        if (s_side) {
            cudaEventCreateWithFlags(&ev_fork, cudaEventDisableTiming);
            cudaEventCreateWithFlags(&ev_join, cudaEventDisableTiming);
        }
    }

    prep_small<<<18, 256>>>(bq, bk, bv);
    prep_main<<<1536, 256>>>((const float2*)x, (const float2*)wq,
                             (const float2*)wk, (const float2*)wv);

    if (s_side) {
        cudaEventRecord(ev_fork, 0);
        cudaStreamWaitEvent(s_side, ev_fork, 0);
        prep_wo<<<512, 256, 0, s_side>>>((const float2*)wo);
        cudaEventRecord(ev_join, s_side);
    } else {
        prep_wo<<<512, 256>>>((const float2*)wo);
    }

    gemm_h<<<dim3(QKV_N / GBN, T_LEN / GBM), 512, GEMM_SMEM>>>(
        (const __half*)xh, (const __half*)wqkvh, nullptr, (__half*)qkvhp,
        (const float*)bqkvp, QKV_N);

    attn_kernel<<<dim3(T_LEN / AQB, N_HEADS), 256, ATTN_SMEM_BYTES>>>();

    if (s_side) cudaStreamWaitEvent(0, ev_join, 0);

    gemm_h<<<dim3(HID / GBN, T_LEN / GBM), 512, GEMM_SMEM>>>(
        (const __half*)obufhp, (const __half*)woh, out, nullptr, nullptr, HID);
}

// round 9
// speedup vs baseline: 1.0375x; 1.0247x over previous
#include <cuda_runtime.h>
#include <cuda_fp16.h>
#include <mma.h>
#include <math.h>
#include <cstdint>
using namespace nvcuda;

#define T_LEN    2048
#define HID      3584
#define QKV_N    4608
#define N_HEADS  28
#define N_REP    7
#define KDIM     3584
#define SCALE    0.08838834764831845f

// ---------------- device scratch ----------------
__device__ __half g_xh[(size_t)T_LEN * HID];
__device__ __half g_wqkvh[(size_t)QKV_N * HID];
__device__ __half g_woh[(size_t)HID * HID];
__device__ __half g_qkvh[(size_t)T_LEN * QKV_N];
__device__ __half g_obufh[(size_t)T_LEN * HID];
__device__ float  g_bqkv[QKV_N];
__device__ float  g_invfreq[64];

// ---------------- PTX helpers ----------------
__device__ __forceinline__ uint32_t smem_u32(const void* p) {
    uint32_t a;
    asm("{ .reg .u64 t; cvta.to.shared.u64 t, %1; cvt.u32.u64 %0, t; }" : "=r"(a) : "l"(p));
    return a;
}
__device__ __forceinline__ void cp_async16(uint32_t dst, const void* src) {
    asm volatile("cp.async.cg.shared.global [%0], [%1], 16;\n" :: "r"(dst), "l"(src) : "memory");
}
__device__ __forceinline__ void ldsm4(uint32_t* r, uint32_t addr) {
    asm volatile("ldmatrix.sync.aligned.m8n8.x4.shared.b16 {%0,%1,%2,%3}, [%4];"
                 : "=r"(r[0]), "=r"(r[1]), "=r"(r[2]), "=r"(r[3]) : "r"(addr));
}
__device__ __forceinline__ void ldsm4t(uint32_t* r, uint32_t addr) {
    asm volatile("ldmatrix.sync.aligned.m8n8.x4.trans.shared.b16 {%0,%1,%2,%3}, [%4];"
                 : "=r"(r[0]), "=r"(r[1]), "=r"(r[2]), "=r"(r[3]) : "r"(addr));
}
__device__ __forceinline__ void mma16816(float* c, const uint32_t* a, const uint32_t* b) {
    asm volatile(
        "mma.sync.aligned.m16n8k16.row.col.f32.f16.f16.f32 "
        "{%0,%1,%2,%3}, {%4,%5,%6,%7}, {%8,%9}, {%0,%1,%2,%3};"
        : "+f"(c[0]), "+f"(c[1]), "+f"(c[2]), "+f"(c[3])
        : "r"(a[0]), "r"(a[1]), "r"(a[2]), "r"(a[3]), "r"(b[0]), "r"(b[1]));
}

// ---------------- prep (single kernel + small wo kernel) ----------------
__global__ void prep_main(const float2* __restrict__ x,  const float2* __restrict__ wq,
                          const float2* __restrict__ wk, const float2* __restrict__ wv,
                          const float* __restrict__ bq,  const float* __restrict__ bk,
                          const float* __restrict__ bv) {
    // small one-time tables handled by block 0
    if (blockIdx.x == 0) {
        if (threadIdx.x < 64)
            g_invfreq[threadIdx.x] = (float)exp(-(double)threadIdx.x / 64.0 * log(10000.0));
        for (int i = threadIdx.x; i < QKV_N; i += 256) {
            if (i < 3584) g_bqkv[i] = bq[i];
            else if (i < 4096) g_bqkv[i] = bk[i - 3584];
            else g_bqkv[i] = bv[i - 4096];
        }
    }
    const size_t NX  = (size_t)T_LEN * HID / 2;
    const size_t NWQ = (size_t)HID * HID / 2;
    const size_t NWK = (size_t)512 * HID / 2;
    const size_t TOT = NX + NWQ + 2 * NWK;
    __half2* dx  = (__half2*)g_xh;
    __half2* dwq = (__half2*)g_wqkvh;
    __half2* dwk = (__half2*)(g_wqkvh + (size_t)3584 * HID);
    __half2* dwv = (__half2*)(g_wqkvh + (size_t)4096 * HID);
    size_t stride = (size_t)gridDim.x * blockDim.x;
    for (size_t i = (size_t)blockIdx.x * blockDim.x + threadIdx.x; i < TOT; i += stride) {
        size_t o = i;
        const float2* s; __half2* d;
        if (o < NX)                { s = x;  d = dx;  }
        else if ((o -= NX)  < NWQ) { s = wq; d = dwq; }
        else if ((o -= NWQ) < NWK) { s = wk; d = dwk; }
        else { o -= NWK;             s = wv; d = dwv; }
        float2 v = s[o];
        d[o] = __floats2half2_rn(v.x, v.y);
    }
}

__global__ void prep_wo(const float2* __restrict__ wo) {
    const size_t N = (size_t)HID * HID / 2;
    __half2* d = (__half2*)g_woh;
    size_t stride = (size_t)gridDim.x * blockDim.x;
    for (size_t i = (size_t)blockIdx.x * blockDim.x + threadIdx.x; i < N; i += stride) {
        float2 v = wo[i];
        d[i] = __floats2half2_rn(v.x, v.y);
    }
}

// ---------------- GEMM: C = A[M,K]*B[N,K]^T ----------------
// 128x256 CTA tile, 512 threads = 16 warps (2x8), warp tile 64x32,
// BK=64, 3-stage cp.async. Ch path: half out + bias + q-scale + RoPE.
#define GBM 128
#define GBN 256
#define GBK 64
#define GLDA 72
#define GSTAGES 3
#define GSTAGE_H ((GBM + GBN) * GLDA)
#define GSTAGE_BYTES (GSTAGE_H * 2)
#define GEMM_SMEM (GSTAGES * GSTAGE_BYTES)   // 165888
#define GNCHUNK (KDIM / GBK)                 // 56
#define STG_LD 260

__global__ __launch_bounds__(512, 1)
void gemm_h(const __half* __restrict__ A, const __half* __restrict__ B,
            float* __restrict__ Cf, __half* __restrict__ Ch,
            const float* __restrict__ bias, int ldc)
{
    extern __shared__ __half smh[];
    const uint32_t sbase = smem_u32(smh);
    const int tid = threadIdx.x, warp = tid >> 5;
    const int wm = warp >> 3, wn = warp & 7;

    const long m0 = (long)blockIdx.y * GBM;
    const long n0 = (long)blockIdx.x * GBN;
    const __half* Ab = A + m0 * KDIM;
    const __half* Bb = B + n0 * KDIM;

    wmma::fragment<wmma::accumulator, 16, 16, 16, float> acc[4][2];
    #pragma unroll
    for (int mi = 0; mi < 4; mi++)
        #pragma unroll
        for (int ni = 0; ni < 2; ni++)
            wmma::fill_fragment(acc[mi][ni], 0.0f);

    auto load_chunk = [&](int kc, int s) {
        const __half* ap = Ab + kc * GBK;
        const __half* bp = Bb + kc * GBK;
        uint32_t sA = sbase + s * GSTAGE_BYTES;
        uint32_t sB = sA + GBM * GLDA * 2;
        #pragma unroll
        for (int i = 0; i < 6; i++) {
            int c = tid + i * 512;
            if (c < 1024) {
                int row = c >> 3, seg = (c & 7) * 8;
                cp_async16(sA + (uint32_t)(row * GLDA + seg) * 2, ap + (long)row * KDIM + seg);
            } else {
                int cb = c - 1024;
                int row = cb >> 3, seg = (cb & 7) * 8;
                cp_async16(sB + (uint32_t)(row * GLDA + seg) * 2, bp + (long)row * KDIM + seg);
            }
        }
        asm volatile("cp.async.commit_group;\n" ::: "memory");
    };

    #pragma unroll
    for (int s = 0; s < GSTAGES - 1; s++) load_chunk(s, s);

    for (int k = 0; k < GNCHUNK; k++) {
        if (k < GNCHUNK - 1) {
            asm volatile("cp.async.wait_group 1;\n" ::: "memory");
        } else {
            asm volatile("cp.async.wait_group 0;\n" ::: "memory");
        }
        __syncthreads();
        if (k + GSTAGES - 1 < GNCHUNK) load_chunk(k + GSTAGES - 1, (k + GSTAGES - 1) % GSTAGES);

        const __half* As = smh + (size_t)(k % GSTAGES) * GSTAGE_H;
        const __half* Bs = As + GBM * GLDA;
        #pragma unroll
        for (int kk = 0; kk < 4; kk++) {
            wmma::fragment<wmma::matrix_a, 16, 16, 16, __half, wmma::row_major> af[4];
            #pragma unroll
            for (int mi = 0; mi < 4; mi++)
                wmma::load_matrix_sync(af[mi], As + (wm * 64 + mi * 16) * GLDA + kk * 16, GLDA);
            #pragma unroll
            for (int ni = 0; ni < 2; ni++) {
                wmma::fragment<wmma::matrix_b, 16, 16, 16, __half, wmma::col_major> bf;
                wmma::load_matrix_sync(bf, Bs + (wn * 32 + ni * 16) * GLDA + kk * 16, GLDA);
                #pragma unroll
                for (int mi = 0; mi < 4; mi++)
                    wmma::mma_sync(acc[mi][ni], af[mi], bf, acc[mi][ni]);
            }
        }
    }

    __syncthreads();

    if (Ch) {
        float* stg = (float*)smh;
        #pragma unroll
        for (int mi = 0; mi < 4; mi++)
            #pragma unroll
            for (int ni = 0; ni < 2; ni++)
                wmma::store_matrix_sync(stg + (wm * 64 + mi * 16) * STG_LD + wn * 32 + ni * 16,
                                        acc[mi][ni], STG_LD, wmma::mem_row_major);
        __syncthreads();

        for (int u = tid; u < 128 * 2 * 16; u += 512) {
            int r  = u >> 5;
            int hb = (u >> 4) & 1;
            int i4 = (u & 15) * 4;
            long col0 = n0 + hb * 128 + i4;
            const float* sp1 = stg + r * STG_LD + hb * 128 + i4;
            const float* sp2 = sp1 + 64;
            float4 x1 = *(const float4*)sp1;
            float4 x2 = *(const float4*)sp2;
            const float* b1 = bias + col0;
            x1.x += b1[0];  x1.y += b1[1];  x1.z += b1[2];  x1.w += b1[3];
            x2.x += b1[64]; x2.y += b1[65]; x2.z += b1[66]; x2.w += b1[67];
            if (col0 < 3584) {   // q heads: fold softmax scale into q
                x1.x *= SCALE; x1.y *= SCALE; x1.z *= SCALE; x1.w *= SCALE;
                x2.x *= SCALE; x2.y *= SCALE; x2.z *= SCALE; x2.w *= SCALE;
            }
            long gr = m0 + r;
            __half2 o1a, o1b, o2a, o2b;
            if (col0 < 4096) {   // q + k heads: rope (rotation commutes with scale)
                float t = (float)gr;
                float s0, c0, s1c, c1, s2, c2, s3, c3;
                sincosf(t * g_invfreq[i4 + 0], &s0, &c0);
                sincosf(t * g_invfreq[i4 + 1], &s1c, &c1);
                sincosf(t * g_invfreq[i4 + 2], &s2, &c2);
                sincosf(t * g_invfreq[i4 + 3], &s3, &c3);
                o1a = __floats2half2_rn(x1.x * c0 - x2.x * s0,  x1.y * c1 - x2.y * s1c);
                o1b = __floats2half2_rn(x1.z * c2 - x2.z * s2,  x1.w * c3 - x2.w * s3);
                o2a = __floats2half2_rn(x2.x * c0 + x1.x * s0,  x2.y * c1 + x1.y * s1c);
                o2b = __floats2half2_rn(x2.z * c2 + x1.z * s2,  x2.w * c3 + x1.w * s3);
            } else {
                o1a = __floats2half2_rn(x1.x, x1.y);
                o1b = __floats2half2_rn(x1.z, x1.w);
                o2a = __floats2half2_rn(x2.x, x2.y);
                o2b = __floats2half2_rn(x2.z, x2.w);
            }
            __half* d1 = Ch + gr * (long)ldc + col0;
            uint2 w1; w1.x = *(uint32_t*)&o1a; w1.y = *(uint32_t*)&o1b;
            uint2 w2; w2.x = *(uint32_t*)&o2a; w2.y = *(uint32_t*)&o2b;
            *(uint2*)d1 = w1;
            *(uint2*)(d1 + 64) = w2;
        }
    } else {
        #pragma unroll
        for (int mi = 0; mi < 4; mi++)
            #pragma unroll
            for (int ni = 0; ni < 2; ni++) {
                float* cp = Cf + (m0 + wm * 64 + mi * 16) * (long)ldc + n0 + wn * 32 + ni * 16;
                wmma::store_matrix_sync(cp, acc[mi][ni], ldc, wmma::mem_row_major);
            }
    }
}

// ---------------- FA2-style attention: AKB=128 (halved softmax overhead) ----------------
#define AQB 128
#define AKB 128
#define LDK 136
#define ATTN_SMEM_BYTES ((AQB * LDK + 2 * 2 * AKB * LDK) * 2)   // 174080

__global__ __launch_bounds__(256)
void attn_kernel()
{
    extern __shared__ __half sm[];
    const uint32_t sbase = smem_u32(sm);
    const int qb = blockIdx.x, h = blockIdx.y, kvh = h / N_REP;
    const int tid = threadIdx.x, w = tid >> 5, lane = tid & 31;

    const __half* qg = g_qkvh + (size_t)(qb * AQB) * QKV_N + h * 128;
    #pragma unroll
    for (int i = 0; i < 8; i++) {
        int lin = tid + i * 256;
        int r = lin >> 4, seg = (lin & 15) * 8;
        *(uint4*)&sm[r * LDK + seg] = *(const uint4*)(qg + (size_t)r * QKV_N + seg);
    }

    auto kvload = [&](int kb, int s) {
        const __half* kg = g_qkvh + (size_t)(kb * AKB) * QKV_N + 3584 + kvh * 128;
        const __half* vg = g_qkvh + (size_t)(kb * AKB) * QKV_N + 4096 + kvh * 128;
        uint32_t kb_s = sbase + (uint32_t)(AQB * LDK + s * 2 * AKB * LDK) * 2;
        uint32_t vb_s = kb_s + AKB * LDK * 2;
        #pragma unroll
        for (int i = 0; i < 8; i++) {
            int lin = tid + i * 256;
            int r = lin >> 4, seg = (lin & 15) * 8;
            uint32_t off = (uint32_t)(r * LDK + seg) * 2;
            cp_async16(kb_s + off, kg + (size_t)r * QKV_N + seg);
            cp_async16(vb_s + off, vg + (size_t)r * QKV_N + seg);
        }
        asm volatile("cp.async.commit_group;\n" ::: "memory");
    };
    kvload(0, 0);
    __syncthreads();

    uint32_t qf[8][4];
    {
        int quad = lane >> 3, r = lane & 7;
        int qrow = w * 16 + (quad & 1) * 8 + r;
        #pragma unroll
        for (int kk = 0; kk < 8; kk++) {
            uint32_t addr = sbase + (uint32_t)(qrow * LDK + kk * 16 + (quad >> 1) * 8) * 2;
            ldsm4(qf[kk], addr);
        }
    }

    float of[16][4];
    #pragma unroll
    for (int j = 0; j < 16; j++) { of[j][0] = of[j][1] = of[j][2] = of[j][3] = 0.f; }
    float m0 = -INFINITY, m1 = -INFINITY, l0 = 0.f, l1 = 0.f;

    const int quad = lane >> 3, r8 = lane & 7;
    const int k_rowoff = (quad >> 1) * 8 + r8;
    const int k_coloff = (quad & 1) * 8;
    const int v_rowoff = (quad & 1) * 8 + r8;
    const int v_coloff = (quad >> 1) * 8;

    for (int kb = 0; kb < T_LEN / AKB; kb++) {
        if (kb + 1 < T_LEN / AKB) {
            kvload(kb + 1, (kb + 1) & 1);
            asm volatile("cp.async.wait_group 1;\n" ::: "memory");
        } else {
            asm volatile("cp.async.wait_group 0;\n" ::: "memory");
        }
        __syncthreads();

        uint32_t kbase = sbase + (uint32_t)(AQB * LDK + (kb & 1) * 2 * AKB * LDK) * 2;
        uint32_t vbase = kbase + AKB * LDK * 2;

        // S = Q K^T : m16 x n128 per warp (q pre-scaled in GEMM epilogue)
        float sf[16][4];
        #pragma unroll
        for (int j = 0; j < 16; j++) { sf[j][0] = sf[j][1] = sf[j][2] = sf[j][3] = 0.f; }
        #pragma unroll
        for (int jp = 0; jp < 8; jp++) {
            #pragma unroll
            for (int kk = 0; kk < 8; kk++) {
                uint32_t addr = kbase + (uint32_t)((jp * 16 + k_rowoff) * LDK + kk * 16 + k_coloff) * 2;
                uint32_t b[4];
                ldsm4(b, addr);
                mma16816(sf[2 * jp],     qf[kk], b);
                mma16816(sf[2 * jp + 1], qf[kk], b + 2);
            }
        }

        float mx0 = -INFINITY, mx1 = -INFINITY;
        #pragma unroll
        for (int j = 0; j < 16; j++) {
            mx0 = fmaxf(mx0, fmaxf(sf[j][0], sf[j][1]));
            mx1 = fmaxf(mx1, fmaxf(sf[j][2], sf[j][3]));
        }
        mx0 = fmaxf(mx0, __shfl_xor_sync(0xffffffffu, mx0, 1));
        mx0 = fmaxf(mx0, __shfl_xor_sync(0xffffffffu, mx0, 2));
        mx1 = fmaxf(mx1, __shfl_xor_sync(0xffffffffu, mx1, 1));
        mx1 = fmaxf(mx1, __shfl_xor_sync(0xffffffffu, mx1, 2));

        float mn0 = fmaxf(m0, mx0);
        float mn1 = fmaxf(m1, mx1);
        float a0 = __expf(m0 - mn0);
        float a1 = __expf(m1 - mn1);

        // exp + pack directly into PV A-fragment layout
        uint32_t pa[8][4];
        float s0 = 0.f, s1 = 0.f;
        #pragma unroll
        for (int j = 0; j < 16; j++) {
            float p0 = __expf(sf[j][0] - mn0);
            float p1 = __expf(sf[j][1] - mn0);
            float p2 = __expf(sf[j][2] - mn1);
            float p3 = __expf(sf[j][3] - mn1);
            s0 += p0 + p1; s1 += p2 + p3;
            __half2 h01 = __floats2half2_rn(p0, p1);
            __half2 h23 = __floats2half2_rn(p2, p3);
            pa[j >> 1][(j & 1) * 2]     = *(uint32_t*)&h01;
            pa[j >> 1][(j & 1) * 2 + 1] = *(uint32_t*)&h23;
        }
        s0 += __shfl_xor_sync(0xffffffffu, s0, 1);
        s0 += __shfl_xor_sync(0xffffffffu, s0, 2);
        s1 += __shfl_xor_sync(0xffffffffu, s1, 1);
        s1 += __shfl_xor_sync(0xffffffffu, s1, 2);
        l0 = l0 * a0 + s0;
        l1 = l1 * a1 + s1;
        m0 = mn0; m1 = mn1;

        #pragma unroll
        for (int j = 0; j < 16; j++) {
            of[j][0] *= a0; of[j][1] *= a0;
            of[j][2] *= a1; of[j][3] *= a1;
        }

        // O += P V : k = 128 kv rows = 8 k-blocks
        #pragma unroll
        for (int jp = 0; jp < 8; jp++) {
            #pragma unroll
            for (int kk = 0; kk < 8; kk++) {
                uint32_t addr = vbase + (uint32_t)((kk * 16 + v_rowoff) * LDK + jp * 16 + v_coloff) * 2;
                uint32_t b[4];
                ldsm4t(b, addr);
                mma16816(of[2 * jp],     pa[kk], b);
                mma16816(of[2 * jp + 1], pa[kk], b + 2);
            }
        }
        __syncthreads();
    }

    float inv0 = 1.f / l0, inv1 = 1.f / l1;
    int row_lo = qb * AQB + w * 16 + (lane >> 2);
    int tig = lane & 3;
    #pragma unroll
    for (int j = 0; j < 16; j++) {
        int col = h * 128 + j * 8 + tig * 2;
        __half2 o01 = __floats2half2_rn(of[j][0] * inv0, of[j][1] * inv0);
        __half2 o23 = __floats2half2_rn(of[j][2] * inv1, of[j][3] * inv1);
        *(__half2*)&g_obufh[(size_t)row_lo * HID + col] = o01;
        *(__half2*)&g_obufh[(size_t)(row_lo + 8) * HID + col] = o23;
    }
}

// ---------------- launch ----------------
extern "C" void kernel_launch(void* const* d_in, const int* in_sizes, int n_in,
                              void* d_out, int out_size)
{
    (void)in_sizes; (void)n_in; (void)out_size;
    const float* x  = (const float*)d_in[1];
    const float* wq = (const float*)d_in[2];
    const float* bq = (const float*)d_in[3];
    const float* wk = (const float*)d_in[4];
    const float* bk = (const float*)d_in[5];
    const float* wv = (const float*)d_in[6];
    const float* bv = (const float*)d_in[7];
    const float* wo = (const float*)d_in[8];
    float* out = (float*)d_out;

    void *xh, *wqkvh, *woh, *qkvhp, *obufhp, *bqkvp;
    cudaGetSymbolAddress(&xh, g_xh);
    cudaGetSymbolAddress(&wqkvh, g_wqkvh);
    cudaGetSymbolAddress(&woh, g_woh);
    cudaGetSymbolAddress(&qkvhp, g_qkvh);
    cudaGetSymbolAddress(&obufhp, g_obufh);
    cudaGetSymbolAddress(&bqkvp, g_bqkv);

    cudaFuncSetAttribute(gemm_h, cudaFuncAttributeMaxDynamicSharedMemorySize, GEMM_SMEM);
    cudaFuncSetAttribute(attn_kernel, cudaFuncAttributeMaxDynamicSharedMemorySize, ATTN_SMEM_BYTES);

    static cudaStream_t s_side = nullptr;
    static cudaEvent_t ev_fork = nullptr, ev_join = nullptr;
    if (!s_side) {
        if (cudaStreamCreateWithFlags(&s_side, cudaStreamNonBlocking) != cudaSuccess) s_side = nullptr;
        if (s_side) {
            cudaEventCreateWithFlags(&ev_fork, cudaEventDisableTiming);
            cudaEventCreateWithFlags(&ev_join, cudaEventDisableTiming);
        }
    }

    prep_main<<<1536, 256>>>((const float2*)x, (const float2*)wq,
                             (const float2*)wk, (const float2*)wv, bq, bk, bv);

    if (s_side) {
        cudaEventRecord(ev_fork, 0);
        cudaStreamWaitEvent(s_side, ev_fork, 0);
        prep_wo<<<512, 256, 0, s_side>>>((const float2*)wo);
        cudaEventRecord(ev_join, s_side);
    } else {
        prep_wo<<<512, 256>>>((const float2*)wo);
    }

    gemm_h<<<dim3(QKV_N / GBN, T_LEN / GBM), 512, GEMM_SMEM>>>(
        (const __half*)xh, (const __half*)wqkvh, nullptr, (__half*)qkvhp,
        (const float*)bqkvp, QKV_N);

    attn_kernel<<<dim3(T_LEN / AQB, N_HEADS), 256, ATTN_SMEM_BYTES>>>();

    if (s_side) cudaStreamWaitEvent(0, ev_join, 0);

    gemm_h<<<dim3(HID / GBN, T_LEN / GBM), 512, GEMM_SMEM>>>(
        (const __half*)obufhp, (const __half*)woh, out, nullptr, nullptr, HID);
}